// round 7
// baseline (speedup 1.0000x reference)
#include <cuda_runtime.h>
#include <cstdint>
#include <cstddef>

namespace {
constexpr int kB = 16, kS = 2048, kD = 128, TQ = 64, TK = 64, NT = 512;
constexpr int NKT = kS / TK;   // 32
constexpr float kScale = 0.08838834764831845f;  // 1/sqrt(128)

// fragment-major float4 pools (indices in float4 units)
//  QF[s][wr][lane]   s=0..15  idx = s*128 + wr*32 + lane          (2048)
//  KF[s2][jj][lane]  s2=0..7  idx = s2*257 + jj*32 + lane         (2056, padded)
//  VF[s2][jj][lane]  s2=0..3  idx = s2*529 + jj*33 + lane         (2116, padded)
//  PF[s][wr][lane]   s=0..7   idx = s*128 + wr*32 + lane          (1024)
struct Smem {
  float4 QF[2048];
  float4 KF[2056];
  float4 VF[2116];
  float4 PF[1024];
  float Zs[TQ];
  float rZs[TQ];
  float Zp[4][TQ];
  float Vps[4][kD];
  float Vcsum[kD];
};
constexpr int SMEM_BYTES = (int)sizeof(Smem);

__device__ __forceinline__ uint32_t f2tf32(float f) {
  uint32_t u; asm("cvt.rna.tf32.f32 %0, %1;" : "=r"(u) : "f"(f)); return u;
}
__device__ __forceinline__ float tff(float f) {
  return __uint_as_float(f2tf32(f));
}
__device__ __forceinline__ void mma_tf32(float c[4], float4 a, float b0, float b1) {
  asm volatile(
      "mma.sync.aligned.m16n8k8.row.col.f32.tf32.tf32.f32 "
      "{%0,%1,%2,%3}, {%4,%5,%6,%7}, {%8,%9}, {%0,%1,%2,%3};\n"
      : "+f"(c[0]), "+f"(c[1]), "+f"(c[2]), "+f"(c[3])
      : "r"(__float_as_uint(a.x)), "r"(__float_as_uint(a.y)),
        "r"(__float_as_uint(a.z)), "r"(__float_as_uint(a.w)),
        "r"(__float_as_uint(b0)), "r"(__float_as_uint(b1)));
}
}  // namespace

extern "C" __global__ void __launch_bounds__(NT, 1)
sdpa_kernel(const float* __restrict__ Q, const float* __restrict__ K,
            const float* __restrict__ V, float* __restrict__ out,
            float* __restrict__ attn)
{
  extern __shared__ char smem_raw[];
  Smem& sm = *reinterpret_cast<Smem*>(smem_raw);

  const int qt  = blockIdx.x;
  const int b   = blockIdx.y;
  const int tid = threadIdx.x;
  const int q0  = qt * TQ;

  const int wid  = tid >> 5;        // 0..15
  const int lane = tid & 31;
  const int wr   = wid >> 2;        // 0..3 (16-row band)
  const int wc   = wid & 3;         // 0..3 (16 QK cols / 32 PV cols)
  const int gid  = lane >> 2;       // 0..7
  const int tig  = lane & 3;        // 0..3

  const float* Qb = Q + (size_t)b * kS * kD;
  const float* Kb = K + (size_t)b * kS * kD;
  const float* Vb = V + (size_t)b * kS * kD;
  float* outb  = out  + (size_t)b * kS * kD;
  float* attnb = attn + (size_t)b * kS * kS;

  const int r0 = 16 * wr + gid, r1 = r0 + 8;   // mma rows this thread owns

  // ---- prefetch first K/V tile into registers ----
  float4 kreg[4], vreg[4];
  {
    const float4* Kg = reinterpret_cast<const float4*>(Kb + (size_t)qt * TK * kD);
    const float4* Vg = reinterpret_cast<const float4*>(Vb + (size_t)qt * TK * kD);
#pragma unroll
    for (int j = 0; j < 4; ++j) { kreg[j] = Kg[tid + j * NT]; vreg[j] = Vg[tid + j * NT]; }
  }

  // ---- build QF (once): warp (wr,wc) builds s = 4*wc..4*wc+3 ----
  {
    const float* Qr0 = Qb + (size_t)(q0 + r0) * kD;
    const float* Qr1 = Qr0 + 8 * kD;
#pragma unroll
    for (int si = 0; si < 4; ++si) {
      const int s = 4 * wc + si;
      float4 v;
      v.x = tff(Qr0[8 * s + tig]);
      v.y = tff(Qr1[8 * s + tig]);
      v.z = tff(Qr0[8 * s + tig + 4]);
      v.w = tff(Qr1[8 * s + tig + 4]);
      sm.QF[s * 128 + wr * 32 + lane] = v;
    }
  }
  if (tid < TQ) sm.Zs[tid] = (float)q0;   // lower-tile masked ones

  float oacc[4][4];
#pragma unroll
  for (int j = 0; j < 4; ++j)
#pragma unroll
    for (int v = 0; v < 4; ++v) oacc[j][v] = 0.f;

  __syncthreads();   // QF ready

  // ================= Phase 1: upper (incl diagonal) tiles =================
  for (int kt = qt; kt < NKT; ++kt) {
    const int k0 = kt * TK;
    if (kt > qt) __syncthreads();   // previous tile's consumers done

    // ---- stage K -> KF (tf32, fragment-major, conflict-free) ----
    {
      float* kf = reinterpret_cast<float*>(sm.KF);
#pragma unroll
      for (int j = 0; j < 4; ++j) {
        const int f = tid + j * NT;
        const int r = f >> 5, c4 = f & 31;
        const int s2 = c4 >> 2, field = c4 & 3, jj = r >> 3, gr = r & 7;
        const int base = (s2 * 257 + jj * 32 + 4 * gr) * 4 + field;
        kf[base + 0] = tff(kreg[j].x);
        kf[base + 4] = tff(kreg[j].y);
        kf[base + 8] = tff(kreg[j].z);
        kf[base + 12] = tff(kreg[j].w);
      }
    }
    // ---- stage V -> VF (tf32, fragment-major, padded) ----
    {
      float* vf = reinterpret_cast<float*>(sm.VF);
#pragma unroll
      for (int j = 0; j < 4; ++j) {
        const int f = tid + j * NT;
        const int tok = f >> 5, c4 = f & 31;
        const int jj = c4 >> 1, gb = 4 * (c4 & 1);
        const int s2 = tok >> 4, tt = tok & 15;
        const int tigv = tt & 3, fieldv = tt >> 2;
        const int base = (s2 * 529 + jj * 33) * 4 + fieldv;
        vf[base + (4 * (gb + 0) + tigv) * 4] = tff(vreg[j].x);
        vf[base + (4 * (gb + 1) + tigv) * 4] = tff(vreg[j].y);
        vf[base + (4 * (gb + 2) + tigv) * 4] = tff(vreg[j].z);
        vf[base + (4 * (gb + 3) + tigv) * 4] = tff(vreg[j].w);
      }
    }
    // issue next-tile loads early (latency hidden under QK/exp/PV)
    if (kt + 1 < NKT) {
      const float4* Kg = reinterpret_cast<const float4*>(Kb + (size_t)(k0 + TK) * kD);
      const float4* Vg = reinterpret_cast<const float4*>(Vb + (size_t)(k0 + TK) * kD);
#pragma unroll
      for (int j = 0; j < 4; ++j) { kreg[j] = Kg[tid + j * NT]; vreg[j] = Vg[tid + j * NT]; }
    }
    __syncthreads();   // KF/VF ready

    // ---- QK^T: rows 16*wr..+16, cols 16*wc..+16 ----
    float sacc[2][4];
#pragma unroll
    for (int j = 0; j < 2; ++j)
#pragma unroll
      for (int v = 0; v < 4; ++v) sacc[j][v] = 0.f;

#pragma unroll
    for (int s2 = 0; s2 < 8; ++s2) {
      const float4 a0 = sm.QF[(2 * s2) * 128 + wr * 32 + lane];
      const float4 a1 = sm.QF[(2 * s2 + 1) * 128 + wr * 32 + lane];
#pragma unroll
      for (int j = 0; j < 2; ++j) {
        const float4 bf = sm.KF[s2 * 257 + (2 * wc + j) * 32 + lane];
        mma_tf32(sacc[j], a0, bf.x, bf.y);
        mma_tf32(sacc[j], a1, bf.z, bf.w);
      }
    }

    // ---- mask + exp; attn store; PF store (fragment-major); Z partials ----
    const bool diag = (kt == qt);
    float rs0 = 0.f, rs1 = 0.f;
    float* arow0 = attnb + (size_t)(q0 + r0) * kS + k0;
    float* arow1 = attnb + (size_t)(q0 + r1) * kS + k0;
    float* pf = reinterpret_cast<float*>(sm.PF);
#pragma unroll
    for (int j = 0; j < 2; ++j) {
      const int c = 16 * wc + 8 * j + 2 * tig;
      float e00, e01, e10, e11;
      if (diag) {
        e00 = (c     > r0) ? __expf(sacc[j][0] * kScale) : 1.0f;
        e01 = (c + 1 > r0) ? __expf(sacc[j][1] * kScale) : 1.0f;
        e10 = (c     > r1) ? __expf(sacc[j][2] * kScale) : 1.0f;
        e11 = (c + 1 > r1) ? __expf(sacc[j][3] * kScale) : 1.0f;
      } else {
        e00 = __expf(sacc[j][0] * kScale);
        e01 = __expf(sacc[j][1] * kScale);
        e10 = __expf(sacc[j][2] * kScale);
        e11 = __expf(sacc[j][3] * kScale);
      }
      rs0 += e00 + e01;
      rs1 += e10 + e11;
      *reinterpret_cast<float2*>(arow0 + c) = make_float2(e00, e01);
      *reinterpret_cast<float2*>(arow1 + c) = make_float2(e10, e11);
      // PF[sc][wr]: a0=P[r0][k<4], a1=P[r1][k<4], a2=P[r0][k>=4], a3=P[r1][k>=4]
      const int sc = 2 * wc + j;
      const int pbase = (sc * 128 + wr * 32) * 4;
      const int o0 = 2 * tig, o1 = 2 * tig + 1;
      pf[pbase + (4 * gid + (o0 & 3)) * 4 + ((o0 >> 2) << 1) + 0] = tff(e00);
      pf[pbase + (4 * gid + (o1 & 3)) * 4 + ((o1 >> 2) << 1) + 0] = tff(e01);
      pf[pbase + (4 * gid + (o0 & 3)) * 4 + ((o0 >> 2) << 1) + 1] = tff(e10);
      pf[pbase + (4 * gid + (o1 & 3)) * 4 + ((o1 >> 2) << 1) + 1] = tff(e11);
    }
    rs0 += __shfl_xor_sync(0xffffffffu, rs0, 1, 4);
    rs0 += __shfl_xor_sync(0xffffffffu, rs0, 2, 4);
    rs1 += __shfl_xor_sync(0xffffffffu, rs1, 1, 4);
    rs1 += __shfl_xor_sync(0xffffffffu, rs1, 2, 4);
    if (tig == 0) { sm.Zp[wc][r0] = rs0; sm.Zp[wc][r1] = rs1; }
    __syncthreads();   // PF + Zp ready
    if (tid < TQ)
      sm.Zs[tid] += (sm.Zp[0][tid] + sm.Zp[1][tid]) +
                    (sm.Zp[2][tid] + sm.Zp[3][tid]);

    // ---- PV: rows 16*wr..+16, out cols 32*wc..+32 ----
#pragma unroll
    for (int s2 = 0; s2 < 4; ++s2) {
      const float4 a0 = sm.PF[(2 * s2) * 128 + wr * 32 + lane];
      const float4 a1 = sm.PF[(2 * s2 + 1) * 128 + wr * 32 + lane];
#pragma unroll
      for (int j = 0; j < 4; ++j) {
        const float4 bf = sm.VF[s2 * 529 + (4 * wc + j) * 33 + lane];
        mma_tf32(oacc[j], a0, bf.x, bf.y);
        mma_tf32(oacc[j], a1, bf.z, bf.w);
      }
    }
  }

  // ================= Phase 2 =================
  __syncthreads();
  if (tid < TQ) sm.rZs[tid] = 1.0f / sm.Zs[tid];
  __syncthreads();

  // ---- lower-region V column sums (direct gmem, 4-way MLP, deterministic) ----
  {
    const int vc = tid & 127, vq = tid >> 7;
    float a0 = 0.f, a1 = 0.f, a2 = 0.f, a3 = 0.f;
    for (int t = vq; t < q0; t += 16) {
      a0 += Vb[(size_t)t * kD + vc];
      a1 += Vb[(size_t)(t + 4) * kD + vc];
      a2 += Vb[(size_t)(t + 8) * kD + vc];
      a3 += Vb[(size_t)(t + 12) * kD + vc];
    }
    sm.Vps[vq][vc] = (a0 + a1) + (a2 + a3);
  }

  // ---- lower attn fill = 1/Z ----
  const int ftr = tid >> 4, ftc = tid & 15;   // 32 row-slots x 16 float4 cols
  for (int kt = 0; kt < qt; ++kt) {
    const int k0 = kt * TK;
#pragma unroll
    for (int p = 0; p < 2; ++p) {
      const int r = ftr + 32 * p;
      const float rz = sm.rZs[r];
      *reinterpret_cast<float4*>(&attnb[(size_t)(q0 + r) * kS + k0 + 4 * ftc]) =
          make_float4(rz, rz, rz, rz);
    }
  }
  __syncthreads();
  if (tid < kD)
    sm.Vcsum[tid] = (sm.Vps[0][tid] + sm.Vps[1][tid]) +
                    (sm.Vps[2][tid] + sm.Vps[3][tid]);
  __syncthreads();

  // ---- rescale upper attn tiles: attn *= 1/Z ----
  for (int kt = qt; kt < NKT; ++kt) {
    const int k0 = kt * TK;
#pragma unroll
    for (int p = 0; p < 2; ++p) {
      const int r = ftr + 32 * p;
      const float rz = sm.rZs[r];
      float4* a = reinterpret_cast<float4*>(
          &attnb[(size_t)(q0 + r) * kS + k0 + 4 * ftc]);
      float4 v = *a;
      v.x *= rz; v.y *= rz; v.z *= rz; v.w *= rz;
      *a = v;
    }
  }

  // ---- final output ----
  {
    const float rz0 = sm.rZs[r0], rz1 = sm.rZs[r1];
#pragma unroll
    for (int j = 0; j < 4; ++j) {
      const int c = 32 * wc + 8 * j + 2 * tig;
      const float vs0 = sm.Vcsum[c], vs1 = sm.Vcsum[c + 1];
      float2 o0 = make_float2(rz0 * (oacc[j][0] + vs0),
                              rz0 * (oacc[j][1] + vs1));
      float2 o1 = make_float2(rz1 * (oacc[j][2] + vs0),
                              rz1 * (oacc[j][3] + vs1));
      *reinterpret_cast<float2*>(&outb[(size_t)(q0 + r0) * kD + c]) = o0;
      *reinterpret_cast<float2*>(&outb[(size_t)(q0 + r1) * kD + c]) = o1;
    }
  }
}

extern "C" void kernel_launch(void* const* d_in, const int* in_sizes, int n_in,
                              void* d_out, int out_size) {
  (void)in_sizes; (void)n_in; (void)out_size;
  const float* Q = (const float*)d_in[0];
  const float* K = (const float*)d_in[1];
  const float* V = (const float*)d_in[2];
  float* out  = (float*)d_out;
  float* attn = out + (size_t)kB * kS * kD;

  cudaFuncSetAttribute(sdpa_kernel, cudaFuncAttributeMaxDynamicSharedMemorySize,
                       SMEM_BYTES);
  dim3 grid(NKT, kB);
  sdpa_kernel<<<grid, NT, SMEM_BYTES>>>(Q, K, V, out, attn);
}

// round 8
// speedup vs baseline: 1.0239x; 1.0239x over previous
#include <cuda_runtime.h>
#include <cstdint>
#include <cstddef>

namespace {
constexpr int kB = 16, kS = 2048, kD = 128, TQ = 64, TK = 64, NT = 512;
constexpr int NKT = kS / TK;   // 32
constexpr int DP = kD + 4;     // K pitch 132 (banks: 4*gid+tig -> conflict-free)
constexpr int VP = kD + 8;     // V pitch 136 (banks: 8*tig+gid -> conflict-free)
constexpr int KP = TK + 4;     // P pitch 68
constexpr float kScale = 0.08838834764831845f;  // 1/sqrt(128)

struct Smem {
  float Ks[2][TK][DP];    // tf32-rounded K tiles (G1 double buffer)
  float Vs[2][TK][VP];    // tf32-rounded V tiles (G2 double buffer)
  float Ps[2][TQ][KP];    // tf32-rounded exp tiles (cross-group, handshaked)
  float Zs[TQ];
  float rZs[TQ];
  float Vps[4][kD];
  float Vcsum[kD];
};
constexpr int SMEM_BYTES = (int)sizeof(Smem);

__device__ __forceinline__ uint32_t f2tf32(float f) {
  uint32_t u; asm("cvt.rna.tf32.f32 %0, %1;" : "=r"(u) : "f"(f)); return u;
}
__device__ __forceinline__ float tff(float f) { return __uint_as_float(f2tf32(f)); }

__device__ __forceinline__ void mma_tf32(float c[4], uint32_t a0, uint32_t a1,
                                         uint32_t a2, uint32_t a3,
                                         float b0, float b1) {
  asm volatile(
      "mma.sync.aligned.m16n8k8.row.col.f32.tf32.tf32.f32 "
      "{%0,%1,%2,%3}, {%4,%5,%6,%7}, {%8,%9}, {%0,%1,%2,%3};\n"
      : "+f"(c[0]), "+f"(c[1]), "+f"(c[2]), "+f"(c[3])
      : "r"(a0), "r"(a1), "r"(a2), "r"(a3),
        "r"(__float_as_uint(b0)), "r"(__float_as_uint(b1)));
}
__device__ __forceinline__ void bar_sync(int id, int cnt) {
  asm volatile("bar.sync %0, %1;" :: "r"(id), "r"(cnt) : "memory");
}
__device__ __forceinline__ void bar_arrive(int id, int cnt) {
  asm volatile("bar.arrive %0, %1;" :: "r"(id), "r"(cnt) : "memory");
}
}  // namespace

extern "C" __global__ void __launch_bounds__(NT, 1)
sdpa_kernel(const float* __restrict__ Q, const float* __restrict__ K,
            const float* __restrict__ V, float* __restrict__ out,
            float* __restrict__ attn)
{
  extern __shared__ char smem_raw[];
  Smem& sm = *reinterpret_cast<Smem*>(smem_raw);

  const int qt  = blockIdx.x;
  const int b   = blockIdx.y;
  const int tid = threadIdx.x;
  const int q0  = qt * TQ;
  const int wid  = tid >> 5;
  const int lane = tid & 31;
  const int gid  = lane >> 2;       // 0..7
  const int tig  = lane & 3;        // 0..3
  const int ntiles = NKT - qt;

  const float* Qb = Q + (size_t)b * kS * kD;
  const float* Kb = K + (size_t)b * kS * kD;
  const float* Vb = V + (size_t)b * kS * kD;
  float* outb  = out  + (size_t)b * kS * kD;
  float* attnb = attn + (size_t)b * kS * kS;

  float oacc[8][4];   // G2 accumulators (declared for both; unused regs pruned per path)
#pragma unroll
  for (int j = 0; j < 8; ++j)
#pragma unroll
    for (int v = 0; v < 4; ++v) oacc[j][v] = 0.f;
  float zrow0 = 0.f, zrow1 = 0.f;

  if (wid < 8) {
    // ================= G1: QK producer =================
    const int wr = wid >> 1;        // 0..3 -> rows 16*wr
    const int wc = wid & 1;         // 0..1 -> cols 32*wc
    const int r0 = 16 * wr + gid, r1 = r0 + 8;

    // Q fragments -> regs (tf32)
    uint32_t qf[16][4];
    {
      const float* Qr0 = Qb + (size_t)(q0 + r0) * kD;
      const float* Qr1 = Qr0 + 8 * kD;
#pragma unroll
      for (int s = 0; s < 16; ++s) {
        const int d = 8 * s + tig;
        qf[s][0] = f2tf32(Qr0[d]);
        qf[s][1] = f2tf32(Qr1[d]);
        qf[s][2] = f2tf32(Qr0[d + 4]);
        qf[s][3] = f2tf32(Qr1[d + 4]);
      }
    }
    // stage K[qt] -> Ks[0] (tf32)
    {
      const float4* Kg = reinterpret_cast<const float4*>(Kb + (size_t)qt * TK * kD);
#pragma unroll
      for (int j = 0; j < 8; ++j) {
        const int f = tid + j * 256;
        const int r = f >> 5, c4 = f & 31;
        float4 v = Kg[f];
        float4 t = make_float4(tff(v.x), tff(v.y), tff(v.z), tff(v.w));
        *reinterpret_cast<float4*>(&sm.Ks[0][r][c4 * 4]) = t;
      }
    }
    bar_sync(1, 256);

    for (int i = 0; i < ntiles; ++i) {
      const int kt = qt + i, k0 = kt * TK, buf = i & 1;

      // issue next K loads early (latency hidden under MMAs/exp)
      float4 kreg[8];
      if (i + 1 < ntiles) {
        const float4* Kg = reinterpret_cast<const float4*>(Kb + (size_t)(k0 + TK) * kD);
#pragma unroll
        for (int j = 0; j < 8; ++j) kreg[j] = Kg[tid + j * 256];
      }

      // QK^T: rows 16wr..+16, cols 32wc..+32
      float sacc[4][4];
#pragma unroll
      for (int j = 0; j < 4; ++j)
#pragma unroll
        for (int v = 0; v < 4; ++v) sacc[j][v] = 0.f;
      const float (*Kt)[DP] = sm.Ks[buf];
#pragma unroll
      for (int s = 0; s < 16; ++s) {
        const int d0 = 8 * s;
#pragma unroll
        for (int j = 0; j < 4; ++j) {
          const int c0 = 32 * wc + 8 * j + gid;
          mma_tf32(sacc[j], qf[s][0], qf[s][1], qf[s][2], qf[s][3],
                   Kt[c0][d0 + tig], Kt[c0][d0 + tig + 4]);
        }
      }

      if (i >= 2) bar_sync(6 + buf, 512);   // wait Ps[buf] freed by G2

      // mask + exp; attn store (unnormalized); Ps[buf] store (tf32)
      const bool diag = (i == 0);
      float* arow0 = attnb + (size_t)(q0 + r0) * kS + k0;
      float* arow1 = attnb + (size_t)(q0 + r1) * kS + k0;
#pragma unroll
      for (int j = 0; j < 4; ++j) {
        const int c = 32 * wc + 8 * j + 2 * tig;
        float e00, e01, e10, e11;
        if (diag) {
          e00 = (c     > r0) ? __expf(sacc[j][0] * kScale) : 1.0f;
          e01 = (c + 1 > r0) ? __expf(sacc[j][1] * kScale) : 1.0f;
          e10 = (c     > r1) ? __expf(sacc[j][2] * kScale) : 1.0f;
          e11 = (c + 1 > r1) ? __expf(sacc[j][3] * kScale) : 1.0f;
        } else {
          e00 = __expf(sacc[j][0] * kScale);
          e01 = __expf(sacc[j][1] * kScale);
          e10 = __expf(sacc[j][2] * kScale);
          e11 = __expf(sacc[j][3] * kScale);
        }
        *reinterpret_cast<float2*>(arow0 + c) = make_float2(e00, e01);
        *reinterpret_cast<float2*>(arow1 + c) = make_float2(e10, e11);
        *reinterpret_cast<float2*>(&sm.Ps[buf][r0][c]) = make_float2(tff(e00), tff(e01));
        *reinterpret_cast<float2*>(&sm.Ps[buf][r1][c]) = make_float2(tff(e10), tff(e11));
      }
      __threadfence_block();
      bar_arrive(4 + buf, 512);             // publish Ps[buf]

      // stage K[i+1] -> other buffer
      if (i + 1 < ntiles) {
#pragma unroll
        for (int j = 0; j < 8; ++j) {
          const int f = tid + j * 256;
          const int r = f >> 5, c4 = f & 31;
          float4 t = make_float4(tff(kreg[j].x), tff(kreg[j].y),
                                 tff(kreg[j].z), tff(kreg[j].w));
          *reinterpret_cast<float4*>(&sm.Ks[buf ^ 1][r][c4 * 4]) = t;
        }
      }
      bar_sync(1, 256);
    }
  } else {
    // ================= G2: PV consumer =================
    const int tid2 = tid - 256;
    const int w2 = wid - 8;
    const int wr = w2 >> 1;         // rows 16*wr
    const int wc = w2 & 1;          // cols 64*wc
    const int r0 = 16 * wr + gid, r1 = r0 + 8;

    // stage V[qt] -> Vs[0] (tf32)
    {
      const float4* Vg = reinterpret_cast<const float4*>(Vb + (size_t)qt * TK * kD);
#pragma unroll
      for (int j = 0; j < 8; ++j) {
        const int f = tid2 + j * 256;
        const int r = f >> 5, c4 = f & 31;
        float4 v = Vg[f];
        float4 t = make_float4(tff(v.x), tff(v.y), tff(v.z), tff(v.w));
        *reinterpret_cast<float4*>(&sm.Vs[0][r][c4 * 4]) = t;
      }
    }
    bar_sync(2, 256);

    for (int i = 0; i < ntiles; ++i) {
      const int kt = qt + i, k0 = kt * TK, buf = i & 1;

      float4 vreg[8];
      if (i + 1 < ntiles) {
        const float4* Vg = reinterpret_cast<const float4*>(Vb + (size_t)(k0 + TK) * kD);
#pragma unroll
        for (int j = 0; j < 8; ++j) vreg[j] = Vg[tid2 + j * 256];
      }

      bar_sync(4 + buf, 512);              // wait Ps[buf] full

      const float (*Pt)[KP] = sm.Ps[buf];
      const float (*Vt)[VP] = sm.Vs[buf];
#pragma unroll
      for (int kk = 0; kk < TK; kk += 8) {
        const float a0f = Pt[r0][kk + tig];
        const float a1f = Pt[r1][kk + tig];
        const float a2f = Pt[r0][kk + tig + 4];
        const float a3f = Pt[r1][kk + tig + 4];
        if (wc == 0) { zrow0 += a0f + a2f; zrow1 += a1f + a3f; }
        const uint32_t a0 = __float_as_uint(a0f), a1 = __float_as_uint(a1f);
        const uint32_t a2 = __float_as_uint(a2f), a3 = __float_as_uint(a3f);
#pragma unroll
        for (int j = 0; j < 8; ++j) {
          const int c0 = 64 * wc + 8 * j + gid;
          asm volatile(
              "mma.sync.aligned.m16n8k8.row.col.f32.tf32.tf32.f32 "
              "{%0,%1,%2,%3}, {%4,%5,%6,%7}, {%8,%9}, {%0,%1,%2,%3};\n"
              : "+f"(oacc[j][0]), "+f"(oacc[j][1]), "+f"(oacc[j][2]), "+f"(oacc[j][3])
              : "r"(a0), "r"(a1), "r"(a2), "r"(a3),
                "r"(__float_as_uint(Vt[kk + tig][c0])),
                "r"(__float_as_uint(Vt[kk + tig + 4][c0])));
        }
      }
      bar_arrive(6 + buf, 512);            // free Ps[buf]

      if (i + 1 < ntiles) {
#pragma unroll
        for (int j = 0; j < 8; ++j) {
          const int f = tid2 + j * 256;
          const int r = f >> 5, c4 = f & 31;
          float4 t = make_float4(tff(vreg[j].x), tff(vreg[j].y),
                                 tff(vreg[j].z), tff(vreg[j].w));
          *reinterpret_cast<float4*>(&sm.Vs[buf ^ 1][r][c4 * 4]) = t;
        }
      }
      bar_sync(2, 256);
    }

    // Z finalize: quad-reduce, one owner per row
    zrow0 += __shfl_xor_sync(0xffffffffu, zrow0, 1, 4);
    zrow0 += __shfl_xor_sync(0xffffffffu, zrow0, 2, 4);
    zrow1 += __shfl_xor_sync(0xffffffffu, zrow1, 1, 4);
    zrow1 += __shfl_xor_sync(0xffffffffu, zrow1, 2, 4);
    if (wc == 0 && tig == 0) {
      sm.Zs[r0] = (float)q0 + zrow0;
      sm.Zs[r1] = (float)q0 + zrow1;
    }
  }

  // ================= Phase 2 (all 512 threads) =================
  __syncthreads();
  if (tid < TQ) sm.rZs[tid] = 1.0f / sm.Zs[tid];
  __syncthreads();

  // lower-region V column sums (gmem streaming, 4-way MLP, deterministic)
  {
    const int vc = tid & 127, vq = tid >> 7;
    float a0 = 0.f, a1 = 0.f, a2 = 0.f, a3 = 0.f;
    for (int t = vq; t < q0; t += 16) {
      a0 += Vb[(size_t)t * kD + vc];
      a1 += Vb[(size_t)(t + 4) * kD + vc];
      a2 += Vb[(size_t)(t + 8) * kD + vc];
      a3 += Vb[(size_t)(t + 12) * kD + vc];
    }
    sm.Vps[vq][vc] = (a0 + a1) + (a2 + a3);
  }

  // lower attn fill = 1/Z
  const int ftr = tid >> 4, ftc = tid & 15;
  for (int kt = 0; kt < qt; ++kt) {
    const int k0 = kt * TK;
#pragma unroll
    for (int p = 0; p < 2; ++p) {
      const int r = ftr + 32 * p;
      const float rz = sm.rZs[r];
      *reinterpret_cast<float4*>(&attnb[(size_t)(q0 + r) * kS + k0 + 4 * ftc]) =
          make_float4(rz, rz, rz, rz);
    }
  }
  __syncthreads();
  if (tid < kD)
    sm.Vcsum[tid] = (sm.Vps[0][tid] + sm.Vps[1][tid]) +
                    (sm.Vps[2][tid] + sm.Vps[3][tid]);
  __syncthreads();

  // rescale upper attn tiles: attn *= 1/Z
  for (int kt = qt; kt < NKT; ++kt) {
    const int k0 = kt * TK;
#pragma unroll
    for (int p = 0; p < 2; ++p) {
      const int r = ftr + 32 * p;
      const float rz = sm.rZs[r];
      float4* a = reinterpret_cast<float4*>(
          &attnb[(size_t)(q0 + r) * kS + k0 + 4 * ftc]);
      float4 v = *a;
      v.x *= rz; v.y *= rz; v.z *= rz; v.w *= rz;
      *a = v;
    }
  }

  // final output (G2 warps own oacc)
  if (wid >= 8) {
    const int w2 = wid - 8;
    const int wr = w2 >> 1, wc = w2 & 1;
    const int r0 = 16 * wr + gid, r1 = r0 + 8;
    const float rz0 = sm.rZs[r0], rz1 = sm.rZs[r1];
#pragma unroll
    for (int j = 0; j < 8; ++j) {
      const int c = 64 * wc + 8 * j + 2 * tig;
      const float vs0 = sm.Vcsum[c], vs1 = sm.Vcsum[c + 1];
      float2 o0 = make_float2(rz0 * (oacc[j][0] + vs0),
                              rz0 * (oacc[j][1] + vs1));
      float2 o1 = make_float2(rz1 * (oacc[j][2] + vs0),
                              rz1 * (oacc[j][3] + vs1));
      *reinterpret_cast<float2*>(&outb[(size_t)(q0 + r0) * kD + c]) = o0;
      *reinterpret_cast<float2*>(&outb[(size_t)(q0 + r1) * kD + c]) = o1;
    }
  }
}

extern "C" void kernel_launch(void* const* d_in, const int* in_sizes, int n_in,
                              void* d_out, int out_size) {
  (void)in_sizes; (void)n_in; (void)out_size;
  const float* Q = (const float*)d_in[0];
  const float* K = (const float*)d_in[1];
  const float* V = (const float*)d_in[2];
  float* out  = (float*)d_out;
  float* attn = out + (size_t)kB * kS * kD;

  cudaFuncSetAttribute(sdpa_kernel, cudaFuncAttributeMaxDynamicSharedMemorySize,
                       SMEM_BYTES);
  dim3 grid(NKT, kB);
  sdpa_kernel<<<grid, NT, SMEM_BYTES>>>(Q, K, V, out, attn);
}